// round 2
// baseline (speedup 1.0000x reference)
#include <cuda_runtime.h>

#define D 64
#define NODES_CAP 50000
#define EDGES_CAP 1600000
#define SCAN_BLK 1024

// ---------------- scratch (static device globals; no allocation) ----------------
__device__ int   g_counts[NODES_CAP];
__device__ int   g_roff[NODES_CAP + 1];
__device__ int   g_cursor[NODES_CAP];
__device__ int   g_bsum[64];
__device__ float g_wsum[NODES_CAP];
__device__ int2  g_edge[EDGES_CAP];      // (src, float_as_int(w)) interleaved
__device__ float g_agg[NODES_CAP * D];   // aggregation result per layer
__device__ float g_xn[NODES_CAP * D];    // layer output (next layer's input)

// ---------------- init: hidden = x*temp[0], zero counters ----------------
__global__ void k_init(const float* __restrict__ x, const float* __restrict__ temp,
                       float* __restrict__ hidden, int nd, int n_nodes) {
    int i = blockIdx.x * blockDim.x + threadIdx.x;
    float t0 = temp[0];
    if (i < nd) hidden[i] = x[i] * t0;
    if (i < n_nodes) { g_counts[i] = 0; g_wsum[i] = 0.f; }
}

// ---------------- degree histogram + per-dst weight sum ----------------
__global__ void k_count(const int* __restrict__ dst, const float* __restrict__ w, int E) {
    int e = blockIdx.x * blockDim.x + threadIdx.x;
    if (e < E) {
        int d = __ldg(&dst[e]);
        atomicAdd(&g_counts[d], 1);
        atomicAdd(&g_wsum[d], __ldg(&w[e]));
    }
}

// ---------------- 3-kernel exclusive scan of g_counts -> g_roff ----------------
__global__ void k_scan1(int N) {
    __shared__ int s[SCAN_BLK];
    int tid = threadIdx.x;
    int i = blockIdx.x * SCAN_BLK + tid;
    int v = (i < N) ? g_counts[i] : 0;
    s[tid] = v;
    __syncthreads();
    for (int off = 1; off < SCAN_BLK; off <<= 1) {
        int t = (tid >= off) ? s[tid - off] : 0;
        __syncthreads();
        s[tid] += t;
        __syncthreads();
    }
    if (i < N) g_roff[i] = s[tid] - v;          // block-local exclusive prefix
    if (tid == SCAN_BLK - 1) g_bsum[blockIdx.x] = s[tid];
}

__global__ void k_scan2(int nb) {
    if (threadIdx.x == 0) {
        int acc = 0;
        for (int i = 0; i < nb; i++) { int v = g_bsum[i]; g_bsum[i] = acc; acc += v; }
    }
}

__global__ void k_scan3(int N, int E) {
    int i = blockIdx.x * blockDim.x + threadIdx.x;
    if (i < N) {
        int r = g_roff[i] + g_bsum[i / SCAN_BLK];
        g_roff[i] = r;
        g_cursor[i] = r;
    }
    if (i == 0) g_roff[N] = E;
}

// ---------------- CSR fill: edges sorted by dst, (src,w) interleaved ----------------
__global__ void k_fill(const int* __restrict__ src, const int* __restrict__ dst,
                       const float* __restrict__ w, int E) {
    int e = blockIdx.x * blockDim.x + threadIdx.x;
    if (e < E) {
        int p = atomicAdd(&g_cursor[__ldg(&dst[e])], 1);
        g_edge[p] = make_int2(__ldg(&src[e]), __float_as_int(__ldg(&w[e])));
    }
}

// ---------------- SpMM: one warp per dst node, register accumulate ----------------
// agg[n] = sum over in-edges e of x[src_e] * w_e    (no float atomics)
__global__ void k_spmm(const float2* __restrict__ x0, int use_xn, int N) {
    const float2* __restrict__ xin = use_xn ? (const float2*)g_xn : x0;
    int warp = (blockIdx.x * blockDim.x + threadIdx.x) >> 5;
    int lane = threadIdx.x & 31;
    if (warp >= N) return;
    int beg = __ldg(&g_roff[warp]);
    int end = __ldg(&g_roff[warp + 1]);
    float2 acc = make_float2(0.f, 0.f);
    int e = beg;
    for (; e + 4 <= end; e += 4) {
        int2 e0 = __ldg(&g_edge[e + 0]);
        int2 e1 = __ldg(&g_edge[e + 1]);
        int2 e2 = __ldg(&g_edge[e + 2]);
        int2 e3 = __ldg(&g_edge[e + 3]);
        float2 v0 = __ldg(&xin[e0.x * 32 + lane]);
        float2 v1 = __ldg(&xin[e1.x * 32 + lane]);
        float2 v2 = __ldg(&xin[e2.x * 32 + lane]);
        float2 v3 = __ldg(&xin[e3.x * 32 + lane]);
        float w0 = __int_as_float(e0.y), w1 = __int_as_float(e1.y);
        float w2 = __int_as_float(e2.y), w3 = __int_as_float(e3.y);
        acc.x = fmaf(v0.x, w0, acc.x); acc.y = fmaf(v0.y, w0, acc.y);
        acc.x = fmaf(v1.x, w1, acc.x); acc.y = fmaf(v1.y, w1, acc.y);
        acc.x = fmaf(v2.x, w2, acc.x); acc.y = fmaf(v2.y, w2, acc.y);
        acc.x = fmaf(v3.x, w3, acc.x); acc.y = fmaf(v3.y, w3, acc.y);
    }
    for (; e < end; e++) {
        int2 ee = __ldg(&g_edge[e]);
        float wt = __int_as_float(ee.y);
        float2 v = __ldg(&xin[ee.x * 32 + lane]);
        acc.x = fmaf(v.x, wt, acc.x);
        acc.y = fmaf(v.y, wt, acc.y);
    }
    ((float2*)g_agg)[warp * 32 + lane] = acc;
}

// ---------------- fused GEMM + bias*wsum + relu + hidden accumulation ----------------
// xn[n,o] = relu( sum_d agg[n,d]*W[o,d] + b[o]*wsum[n] )
// hidden[n,o] += xn[n,o] * temp[li+1]
// 64 nodes per block, 256 threads, 4x4 register tile per thread.
__global__ void k_gemm(const float* __restrict__ Wl, const float* __restrict__ bl,
                       const float* __restrict__ temp, int li,
                       float* __restrict__ hidden, int N) {
    __shared__ __align__(16) float As[64][68];   // As[d][n] (transposed agg tile)
    __shared__ __align__(16) float Bs[64][68];   // Bs[d][o] (transposed W)
    int tid = threadIdx.x;
    int bn = blockIdx.x * 64;
    float t = __ldg(&temp[li + 1]);

    for (int idx = tid; idx < 4096; idx += 256) {
        int o = idx >> 6, d = idx & 63;
        Bs[d][o] = __ldg(&Wl[o * 64 + d]);
    }
    for (int idx = tid; idx < 4096; idx += 256) {
        int n = idx >> 6, d = idx & 63;
        int node = bn + n;
        As[d][n] = (node < N) ? g_agg[node * 64 + d] : 0.f;
    }
    __syncthreads();

    int tx = tid & 15;          // output-column tile
    int ty = tid >> 4;          // node tile
    int o0 = tx * 4, n0 = ty * 4;

    float acc[4][4] = {};
    #pragma unroll
    for (int k = 0; k < 64; k++) {
        float4 a = *(const float4*)&As[k][n0];
        float4 b = *(const float4*)&Bs[k][o0];
        acc[0][0] = fmaf(a.x, b.x, acc[0][0]); acc[0][1] = fmaf(a.x, b.y, acc[0][1]);
        acc[0][2] = fmaf(a.x, b.z, acc[0][2]); acc[0][3] = fmaf(a.x, b.w, acc[0][3]);
        acc[1][0] = fmaf(a.y, b.x, acc[1][0]); acc[1][1] = fmaf(a.y, b.y, acc[1][1]);
        acc[1][2] = fmaf(a.y, b.z, acc[1][2]); acc[1][3] = fmaf(a.y, b.w, acc[1][3]);
        acc[2][0] = fmaf(a.z, b.x, acc[2][0]); acc[2][1] = fmaf(a.z, b.y, acc[2][1]);
        acc[2][2] = fmaf(a.z, b.z, acc[2][2]); acc[2][3] = fmaf(a.z, b.w, acc[2][3]);
        acc[3][0] = fmaf(a.w, b.x, acc[3][0]); acc[3][1] = fmaf(a.w, b.y, acc[3][1]);
        acc[3][2] = fmaf(a.w, b.z, acc[3][2]); acc[3][3] = fmaf(a.w, b.w, acc[3][3]);
    }

    float4 bo = *(const float4*)&bl[o0];
    #pragma unroll
    for (int i = 0; i < 4; i++) {
        int node = bn + n0 + i;
        if (node >= N) continue;
        float ws = g_wsum[node];
        float4 r;
        r.x = fmaxf(fmaf(bo.x, ws, acc[i][0]), 0.f);
        r.y = fmaxf(fmaf(bo.y, ws, acc[i][1]), 0.f);
        r.z = fmaxf(fmaf(bo.z, ws, acc[i][2]), 0.f);
        r.w = fmaxf(fmaf(bo.w, ws, acc[i][3]), 0.f);
        *(float4*)&g_xn[node * 64 + o0] = r;
        float4 h = *(float4*)&hidden[node * 64 + o0];
        h.x = fmaf(r.x, t, h.x);
        h.y = fmaf(r.y, t, h.y);
        h.z = fmaf(r.z, t, h.z);
        h.w = fmaf(r.w, t, h.w);
        *(float4*)&hidden[node * 64 + o0] = h;
    }
}

extern "C" void kernel_launch(void* const* d_in, const int* in_sizes, int n_in,
                              void* d_out, int out_size) {
    const float* x    = (const float*)d_in[0];
    const float* w    = (const float*)d_in[1];
    const float* W    = (const float*)d_in[2];
    const float* b    = (const float*)d_in[3];
    const float* temp = (const float*)d_in[4];
    const int*   src  = (const int*)d_in[5];
    const int*   dst  = (const int*)d_in[6];
    float* hidden = (float*)d_out;

    int nd = in_sizes[0];          // N * D
    int N  = nd / D;
    int E  = in_sizes[1];
    int L  = in_sizes[3] / D;

    k_init<<<(nd + 255) / 256, 256>>>(x, temp, hidden, nd, N);
    k_count<<<(E + 255) / 256, 256>>>(dst, w, E);
    int nb = (N + SCAN_BLK - 1) / SCAN_BLK;
    k_scan1<<<nb, SCAN_BLK>>>(N);
    k_scan2<<<1, 32>>>(nb);
    k_scan3<<<(N + 255) / 256, 256>>>(N, E);
    k_fill<<<(E + 255) / 256, 256>>>(src, dst, w, E);

    int spmm_blocks = (N + 7) / 8;            // 8 warps (nodes) per 256-thread block
    int gemm_blocks = (N + 63) / 64;
    for (int i = 0; i < L; i++) {
        k_spmm<<<spmm_blocks, 256>>>((const float2*)x, (i > 0) ? 1 : 0, N);
        k_gemm<<<gemm_blocks, 256>>>(W + i * D * D, b + i * D, temp, i, hidden, N);
    }
}

// round 3
// speedup vs baseline: 1.7206x; 1.7206x over previous
#include <cuda_runtime.h>
#include <cuda_fp16.h>

#define D 64
#define NODES_CAP 50000
#define EDGES_CAP 1600000
#define SCAN_BLK 1024

// ---------------- scratch (static device globals; no allocation) ----------------
__device__ int   g_counts[NODES_CAP];
__device__ int   g_roff[NODES_CAP + 1];
__device__ int   g_cursor[NODES_CAP];
__device__ int   g_bsum[64];
__device__ float g_wsum[NODES_CAP];
__device__ int2  g_edge[EDGES_CAP];                       // (src, float_as_int(w))
__device__ float g_agg[NODES_CAP * D];                    // fp32 aggregation result
__device__ __align__(128) __half2 g_xh[NODES_CAP * 32];   // fp16 feature rows for gather

// ---------------- init: hidden = x*temp[0], xh = fp16(x), zero counters ----------------
__global__ void k_init(const float* __restrict__ x, const float* __restrict__ temp,
                       float* __restrict__ hidden, int nd, int n_nodes) {
    int i = blockIdx.x * blockDim.x + threadIdx.x;
    float t0 = temp[0];
    if (i < nd / 2) {
        float2 v = ((const float2*)x)[i];
        g_xh[i] = __floats2half2_rn(v.x, v.y);
        float2 h = make_float2(v.x * t0, v.y * t0);
        ((float2*)hidden)[i] = h;
    }
    if (i < n_nodes) { g_counts[i] = 0; g_wsum[i] = 0.f; }
}

// ---------------- degree histogram + per-dst weight sum ----------------
__global__ void k_count(const int* __restrict__ dst, const float* __restrict__ w, int E) {
    int e = blockIdx.x * blockDim.x + threadIdx.x;
    if (e < E) {
        int d = __ldg(&dst[e]);
        atomicAdd(&g_counts[d], 1);
        atomicAdd(&g_wsum[d], __ldg(&w[e]));
    }
}

// ---------------- 3-kernel exclusive scan of g_counts -> g_roff ----------------
__global__ void k_scan1(int N) {
    __shared__ int s[SCAN_BLK];
    int tid = threadIdx.x;
    int i = blockIdx.x * SCAN_BLK + tid;
    int v = (i < N) ? g_counts[i] : 0;
    s[tid] = v;
    __syncthreads();
    for (int off = 1; off < SCAN_BLK; off <<= 1) {
        int t = (tid >= off) ? s[tid - off] : 0;
        __syncthreads();
        s[tid] += t;
        __syncthreads();
    }
    if (i < N) g_roff[i] = s[tid] - v;          // block-local exclusive prefix
    if (tid == SCAN_BLK - 1) g_bsum[blockIdx.x] = s[tid];
}

// warp-parallel exclusive scan of up to 64 block sums
__global__ void k_scan2(int nb) {
    int lane = threadIdx.x;
    int v0 = (lane < nb) ? g_bsum[lane] : 0;
    int v1 = (lane + 32 < nb) ? g_bsum[lane + 32] : 0;
    // inclusive warp scan of v0
    int s0 = v0;
    #pragma unroll
    for (int off = 1; off < 32; off <<= 1) {
        int t = __shfl_up_sync(0xffffffffu, s0, off);
        if (lane >= off) s0 += t;
    }
    int tot0 = __shfl_sync(0xffffffffu, s0, 31);
    int s1 = v1;
    #pragma unroll
    for (int off = 1; off < 32; off <<= 1) {
        int t = __shfl_up_sync(0xffffffffu, s1, off);
        if (lane >= off) s1 += t;
    }
    if (lane < nb) g_bsum[lane] = s0 - v0;                       // exclusive
    if (lane + 32 < nb) g_bsum[lane + 32] = tot0 + s1 - v1;
}

__global__ void k_scan3(int N, int E) {
    int i = blockIdx.x * blockDim.x + threadIdx.x;
    if (i < N) {
        int r = g_roff[i] + g_bsum[i / SCAN_BLK];
        g_roff[i] = r;
        g_cursor[i] = r;
    }
    if (i == 0) g_roff[N] = E;
}

// ---------------- CSR fill: edges sorted by dst, (src,w) interleaved ----------------
__global__ void k_fill(const int* __restrict__ src, const int* __restrict__ dst,
                       const float* __restrict__ w, int E) {
    int e = blockIdx.x * blockDim.x + threadIdx.x;
    if (e < E) {
        int p = atomicAdd(&g_cursor[__ldg(&dst[e])], 1);
        g_edge[p] = make_int2(__ldg(&src[e]), __float_as_int(__ldg(&w[e])));
    }
}

// ---------------- SpMM: one warp per dst node, fp16 gather, fp32 accumulate ----------------
// agg[n] = sum over in-edges e of x[src_e] * w_e    (no float atomics)
__global__ void k_spmm(int N) {
    int warp = (blockIdx.x * blockDim.x + threadIdx.x) >> 5;
    int lane = threadIdx.x & 31;
    if (warp >= N) return;
    int beg = __ldg(&g_roff[warp]);
    int end = __ldg(&g_roff[warp + 1]);
    float2 acc = make_float2(0.f, 0.f);
    int e = beg;
    for (; e + 8 <= end; e += 8) {
        int2 ed[8];
        __half2 v[8];
        #pragma unroll
        for (int j = 0; j < 8; j++) ed[j] = __ldg(&g_edge[e + j]);
        #pragma unroll
        for (int j = 0; j < 8; j++) v[j] = __ldg(&g_xh[ed[j].x * 32 + lane]);
        #pragma unroll
        for (int j = 0; j < 8; j++) {
            float wt = __int_as_float(ed[j].y);
            float2 f = __half22float2(v[j]);
            acc.x = fmaf(f.x, wt, acc.x);
            acc.y = fmaf(f.y, wt, acc.y);
        }
    }
    for (; e < end; e++) {
        int2 ee = __ldg(&g_edge[e]);
        float wt = __int_as_float(ee.y);
        float2 f = __half22float2(__ldg(&g_xh[ee.x * 32 + lane]));
        acc.x = fmaf(f.x, wt, acc.x);
        acc.y = fmaf(f.y, wt, acc.y);
    }
    ((float2*)g_agg)[warp * 32 + lane] = acc;
}

// ---------------- fused GEMM + bias*wsum + relu + hidden accumulation ----------------
// xn[n,o] = relu( sum_d agg[n,d]*W[o,d] + b[o]*wsum[n] )  -> stored fp16 in g_xh
// hidden[n,o] += xn[n,o] * temp[li+1]
__global__ void k_gemm(const float* __restrict__ Wl, const float* __restrict__ bl,
                       const float* __restrict__ temp, int li,
                       float* __restrict__ hidden, int N) {
    __shared__ __align__(16) float As[64][68];   // As[d][n]
    __shared__ __align__(16) float Bs[64][68];   // Bs[d][o]
    int tid = threadIdx.x;
    int bn = blockIdx.x * 64;
    float t = __ldg(&temp[li + 1]);

    for (int idx = tid; idx < 4096; idx += 256) {
        int o = idx >> 6, d = idx & 63;
        Bs[d][o] = __ldg(&Wl[o * 64 + d]);
    }
    for (int idx = tid; idx < 4096; idx += 256) {
        int n = idx >> 6, d = idx & 63;
        int node = bn + n;
        As[d][n] = (node < N) ? g_agg[node * 64 + d] : 0.f;
    }
    __syncthreads();

    int tx = tid & 15;          // output-column tile
    int ty = tid >> 4;          // node tile
    int o0 = tx * 4, n0 = ty * 4;

    float acc[4][4] = {};
    #pragma unroll
    for (int k = 0; k < 64; k++) {
        float4 a = *(const float4*)&As[k][n0];
        float4 b = *(const float4*)&Bs[k][o0];
        acc[0][0] = fmaf(a.x, b.x, acc[0][0]); acc[0][1] = fmaf(a.x, b.y, acc[0][1]);
        acc[0][2] = fmaf(a.x, b.z, acc[0][2]); acc[0][3] = fmaf(a.x, b.w, acc[0][3]);
        acc[1][0] = fmaf(a.y, b.x, acc[1][0]); acc[1][1] = fmaf(a.y, b.y, acc[1][1]);
        acc[1][2] = fmaf(a.y, b.z, acc[1][2]); acc[1][3] = fmaf(a.y, b.w, acc[1][3]);
        acc[2][0] = fmaf(a.z, b.x, acc[2][0]); acc[2][1] = fmaf(a.z, b.y, acc[2][1]);
        acc[2][2] = fmaf(a.z, b.z, acc[2][2]); acc[2][3] = fmaf(a.z, b.w, acc[2][3]);
        acc[3][0] = fmaf(a.w, b.x, acc[3][0]); acc[3][1] = fmaf(a.w, b.y, acc[3][1]);
        acc[3][2] = fmaf(a.w, b.z, acc[3][2]); acc[3][3] = fmaf(a.w, b.w, acc[3][3]);
    }

    float4 bo = *(const float4*)&bl[o0];
    #pragma unroll
    for (int i = 0; i < 4; i++) {
        int node = bn + n0 + i;
        if (node >= N) continue;
        float ws = g_wsum[node];
        float4 r;
        r.x = fmaxf(fmaf(bo.x, ws, acc[i][0]), 0.f);
        r.y = fmaxf(fmaf(bo.y, ws, acc[i][1]), 0.f);
        r.z = fmaxf(fmaf(bo.z, ws, acc[i][2]), 0.f);
        r.w = fmaxf(fmaf(bo.w, ws, acc[i][3]), 0.f);
        // fp16 row for next layer's gather
        g_xh[node * 32 + (o0 >> 1) + 0] = __floats2half2_rn(r.x, r.y);
        g_xh[node * 32 + (o0 >> 1) + 1] = __floats2half2_rn(r.z, r.w);
        float4 h = *(float4*)&hidden[node * 64 + o0];
        h.x = fmaf(r.x, t, h.x);
        h.y = fmaf(r.y, t, h.y);
        h.z = fmaf(r.z, t, h.z);
        h.w = fmaf(r.w, t, h.w);
        *(float4*)&hidden[node * 64 + o0] = h;
    }
}

extern "C" void kernel_launch(void* const* d_in, const int* in_sizes, int n_in,
                              void* d_out, int out_size) {
    const float* x    = (const float*)d_in[0];
    const float* w    = (const float*)d_in[1];
    const float* W    = (const float*)d_in[2];
    const float* b    = (const float*)d_in[3];
    const float* temp = (const float*)d_in[4];
    const int*   src  = (const int*)d_in[5];
    const int*   dst  = (const int*)d_in[6];
    float* hidden = (float*)d_out;

    int nd = in_sizes[0];          // N * D
    int N  = nd / D;
    int E  = in_sizes[1];
    int L  = in_sizes[3] / D;

    k_init<<<(nd / 2 + 255) / 256, 256>>>(x, temp, hidden, nd, N);
    k_count<<<(E + 255) / 256, 256>>>(dst, w, E);
    int nb = (N + SCAN_BLK - 1) / SCAN_BLK;
    k_scan1<<<nb, SCAN_BLK>>>(N);
    k_scan2<<<1, 32>>>(nb);
    k_scan3<<<(N + 255) / 256, 256>>>(N, E);
    k_fill<<<(E + 255) / 256, 256>>>(src, dst, w, E);

    int spmm_blocks = (N + 7) / 8;            // 8 warps (nodes) per 256-thread block
    int gemm_blocks = (N + 63) / 64;
    for (int i = 0; i < L; i++) {
        k_spmm<<<spmm_blocks, 256>>>(N);
        k_gemm<<<gemm_blocks, 256>>>(W + i * D * D, b + i * D, temp, i, hidden, N);
    }
}